// round 4
// baseline (speedup 1.0000x reference)
#include <cuda_runtime.h>
#include <cuda_bf16.h>
#include <cstdint>
#include <cstdio>

#define N_ENT 50000
#define N_USR 10000
#define NND   60000
#define NEDGE 1920000
#define NREL  16
#define BATCH 4096
#define NBLK  118   // ceil(NND/512) for the scan

typedef unsigned long long ull;

// packed f32x2 FMA: d.lo += a.lo*b.lo ; d.hi += a.hi*b.hi  (one issue slot, 2 FMAs)
#define FFMA2(d, a, b) asm("fma.rn.f32x2 %0, %1, %2, %0;" : "+l"(d) : "l"(a), "l"(b))

__device__ __forceinline__ float f2lo(ull v) { return __uint_as_float((unsigned)v); }
__device__ __forceinline__ float f2hi(ull v) { return __uint_as_float((unsigned)(v >> 32)); }
__device__ __forceinline__ float f2sum(ull v) { return f2lo(v) + f2hi(v); }
__device__ __forceinline__ float sigmoidf_(float g) { return 1.f / (1.f + __expf(-g)); }

// ---------------- scratch (device globals; no allocation allowed) ----------------
__device__ float g_encoded[NND * 32];
__device__ float g_x1[NND * 32];
__device__ float g_x2[NND * 16];
__device__ float g_agg[NND * 32];   // mean-aggregated neighbor messages
__device__ int   g_cnt[NND];        // degree (zeroed at END of sequence)
__device__ int   g_rowptr[NND];
__device__ int   g_cursor[NND];
__device__ int   g_csr[NEDGE];      // packed: src | (rel<<16)
__device__ int   g_bsum[128];
__device__ float g_gd[NND * 16];
__device__ float g_gs[NND * 16];
__device__ float g_wsum1[NREL * 64];
__device__ float g_wsum2[NREL * 64];
__device__ float g_loss;            // zeroed at END of sequence

extern __shared__ unsigned char dynsmem[];

// ---------------- CSR build --------------------------------------------------------
__global__ void __launch_bounds__(256) count_kernel(const int* __restrict__ edst) {
    int e = blockIdx.x * blockDim.x + threadIdx.x;
    if (e < NEDGE) atomicAdd(&g_cnt[edst[e]], 1);
}

__global__ void __launch_bounds__(512) scan_block_kernel() {
    __shared__ int s[512];
    int gid = blockIdx.x * 512 + threadIdx.x;
    int v = (gid < NND) ? g_cnt[gid] : 0;
    s[threadIdx.x] = v;
    __syncthreads();
#pragma unroll
    for (int off = 1; off < 512; off <<= 1) {
        int t = (threadIdx.x >= off) ? s[threadIdx.x - off] : 0;
        __syncthreads();
        s[threadIdx.x] += t;
        __syncthreads();
    }
    if (gid < NND) g_rowptr[gid] = s[threadIdx.x] - v;   // exclusive within block
    if (threadIdx.x == 511) g_bsum[blockIdx.x] = s[511];
}

// adds the prefix of preceding block sums (reduction per block; NBLK=118 small)
__global__ void __launch_bounds__(512) scan_add_kernel() {
    __shared__ int sred[16];
    int t = threadIdx.x;
    int v = (t < blockIdx.x && t < NBLK) ? g_bsum[t] : 0;   // only t<118 contributes
#pragma unroll
    for (int o = 16; o; o >>= 1) v += __shfl_xor_sync(0xffffffffu, v, o);
    if ((t & 31) == 0) sred[t >> 5] = v;
    __syncthreads();
    if (t < 16) {
        int w = sred[t];
#pragma unroll
        for (int o = 8; o; o >>= 1) w += __shfl_xor_sync(0xffffu, w, o);
        if (t == 0) sred[0] = w;
    }
    __syncthreads();
    int off = sred[0];
    int gid = blockIdx.x * 512 + t;
    if (gid < NND) {
        int r = g_rowptr[gid] + off;
        g_rowptr[gid] = r;
        g_cursor[gid] = r;
    }
}

__global__ void __launch_bounds__(256) fill_kernel(const int* __restrict__ esrc,
                                                   const int* __restrict__ edst,
                                                   const int* __restrict__ erel) {
    int e = blockIdx.x * blockDim.x + threadIdx.x;
    if (e >= NEDGE) return;
    int d = edst[e];
    int slot = atomicAdd(&g_cursor[d], 1);
    g_csr[slot] = esrc[e] | (erel[e] << 16);
}

// ---------------- w_sum = W_r.sum(-1) for both layers ----------------------------
__global__ void __launch_bounds__(256) wsum_kernel(const float* __restrict__ Wr1,
                                                   const float* __restrict__ Wr2) {
    int i = blockIdx.x * blockDim.x + threadIdx.x;
    if (i >= 2 * NREL * 64) return;
    const float* W = (i < NREL * 64) ? Wr1 : Wr2;
    float* o       = (i < NREL * 64) ? g_wsum1 : g_wsum2;
    int j          = i & (NREL * 64 - 1);
    const float* p = W + j * 32;
    float s = 0.f;
#pragma unroll
    for (int t = 0; t < 32; t++) s += p[t];
    o[j] = s;
}

// ---------------- autoencoder: encode ([64]->relu[128]->[32]) --------------------
__global__ void __launch_bounds__(256, 3) encode_kernel(
    const float* __restrict__ ent, const float* __restrict__ usr,
    const float* __restrict__ W0, const float* __restrict__ b0,
    const float* __restrict__ W1, const float* __restrict__ b1) {
    float2* sW0 = (float2*)dynsmem;               // 32 k-pairs x 128 cols  (32 KB)
    float2* sW1 = sW0 + 32 * 128;                 // 64 k-pairs x 32 cols   (16 KB)
    float*  stg = (float*)(sW1 + 64 * 32);        // 8 warps x 512 floats   (16 KB)

    for (int i = threadIdx.x; i < 32 * 128; i += 256) {
        int k2 = i >> 7, j = i & 127;
        sW0[i] = make_float2(W0[(2 * k2) * 128 + j], W0[(2 * k2 + 1) * 128 + j]);
    }
    for (int i = threadIdx.x; i < 64 * 32; i += 256) {
        int k2 = i >> 5, j = i & 31;
        sW1[i] = make_float2(W1[(2 * k2) * 32 + j], W1[(2 * k2 + 1) * 32 + j]);
    }
    __syncthreads();

    const ull* sW0u = (const ull*)sW0;
    const ull* sW1u = (const ull*)sW1;
    const int lane  = threadIdx.x & 31;
    float* mystg    = stg + (threadIdx.x >> 5) * 512;
    ull*   mystgU   = (ull*)mystg;

    const int wid   = (blockIdx.x * 256 + threadIdx.x) >> 5;
    const int nwarp = (gridDim.x * 256) >> 5;

    float bb0[4];
#pragma unroll
    for (int p = 0; p < 4; p++) bb0[p] = b0[lane + 32 * p];
    const float bb1 = b1[lane];

    for (int g = wid; g < NND / 4; g += nwarp) {
#pragma unroll
        for (int m = 0; m < 4; m++) {
            int n = g * 4 + m;
            const float* e = (n < N_ENT) ? (ent + (size_t)n * 64)
                                         : (usr + (size_t)(n - N_ENT) * 64);
            ((float2*)mystg)[m * 32 + lane] = ((const float2*)e)[lane];
        }
        __syncwarp();

        ull acc[4][4];
#pragma unroll
        for (int m = 0; m < 4; m++)
#pragma unroll
            for (int p = 0; p < 4; p++) acc[m][p] = 0ull;
#pragma unroll 8
        for (int k2 = 0; k2 < 32; k2++) {
            ull w0 = sW0u[k2 * 128 + lane];
            ull w1 = sW0u[k2 * 128 + lane + 32];
            ull w2 = sW0u[k2 * 128 + lane + 64];
            ull w3 = sW0u[k2 * 128 + lane + 96];
#pragma unroll
            for (int m = 0; m < 4; m++) {
                ull b = mystgU[m * 32 + k2];
                FFMA2(acc[m][0], b, w0);
                FFMA2(acc[m][1], b, w1);
                FFMA2(acc[m][2], b, w2);
                FFMA2(acc[m][3], b, w3);
            }
        }
        __syncwarp();

#pragma unroll
        for (int m = 0; m < 4; m++)
#pragma unroll
            for (int p = 0; p < 4; p++)
                mystg[m * 128 + lane + 32 * p] = fmaxf(f2sum(acc[m][p]) + bb0[p], 0.f);
        __syncwarp();

        ull a2[4] = {0ull, 0ull, 0ull, 0ull};
#pragma unroll 8
        for (int k2 = 0; k2 < 64; k2++) {
            ull w = sW1u[k2 * 32 + lane];
#pragma unroll
            for (int m = 0; m < 4; m++) {
                ull b = mystgU[m * 64 + k2];
                FFMA2(a2[m], b, w);
            }
        }
#pragma unroll
        for (int m = 0; m < 4; m++)
            g_encoded[(size_t)(g * 4 + m) * 32 + lane] = f2sum(a2[m]) + bb1;
        __syncwarp();
    }
}

// ---------------- autoencoder: decode ([32]->relu[128]->[64]) + sq-err loss ------
__global__ void __launch_bounds__(256, 3) decode_kernel(
    const float* __restrict__ ent, const float* __restrict__ usr,
    const float* __restrict__ W0, const float* __restrict__ b0,
    const float* __restrict__ W1, const float* __restrict__ b1) {
    float2* sW0 = (float2*)dynsmem;               // 16 k-pairs x 128 cols (16 KB)
    float2* sW1 = sW0 + 16 * 128;                 // 64 k-pairs x 64 cols  (32 KB)
    float*  stg = (float*)(sW1 + 64 * 64);        // 8 warps x 512 floats  (16 KB)

    for (int i = threadIdx.x; i < 16 * 128; i += 256) {
        int k2 = i >> 7, j = i & 127;
        sW0[i] = make_float2(W0[(2 * k2) * 128 + j], W0[(2 * k2 + 1) * 128 + j]);
    }
    for (int i = threadIdx.x; i < 64 * 64; i += 256) {
        int k2 = i >> 6, j = i & 63;
        sW1[i] = make_float2(W1[(2 * k2) * 64 + j], W1[(2 * k2 + 1) * 64 + j]);
    }
    __syncthreads();

    const ull* sW0u = (const ull*)sW0;
    const ull* sW1u = (const ull*)sW1;
    const int lane  = threadIdx.x & 31;
    float* mystg    = stg + (threadIdx.x >> 5) * 512;
    ull*   mystgU   = (ull*)mystg;

    const int wid   = (blockIdx.x * 256 + threadIdx.x) >> 5;
    const int nwarp = (gridDim.x * 256) >> 5;

    float bb0[4];
#pragma unroll
    for (int p = 0; p < 4; p++) bb0[p] = b0[lane + 32 * p];
    const float bb1a = b1[lane], bb1b = b1[lane + 32];

    float lsum = 0.f;
    for (int g = wid; g < NND / 4; g += nwarp) {
#pragma unroll
        for (int m = 0; m < 4; m++)
            mystg[m * 32 + lane] = g_encoded[(size_t)(g * 4 + m) * 32 + lane];
        __syncwarp();

        ull acc[4][4];
#pragma unroll
        for (int m = 0; m < 4; m++)
#pragma unroll
            for (int p = 0; p < 4; p++) acc[m][p] = 0ull;
#pragma unroll
        for (int k2 = 0; k2 < 16; k2++) {
            ull w0 = sW0u[k2 * 128 + lane];
            ull w1 = sW0u[k2 * 128 + lane + 32];
            ull w2 = sW0u[k2 * 128 + lane + 64];
            ull w3 = sW0u[k2 * 128 + lane + 96];
#pragma unroll
            for (int m = 0; m < 4; m++) {
                ull b = mystgU[m * 16 + k2];
                FFMA2(acc[m][0], b, w0);
                FFMA2(acc[m][1], b, w1);
                FFMA2(acc[m][2], b, w2);
                FFMA2(acc[m][3], b, w3);
            }
        }
        __syncwarp();
#pragma unroll
        for (int m = 0; m < 4; m++)
#pragma unroll
            for (int p = 0; p < 4; p++)
                mystg[m * 128 + lane + 32 * p] = fmaxf(f2sum(acc[m][p]) + bb0[p], 0.f);
        __syncwarp();

        ull a0[4] = {0ull, 0ull, 0ull, 0ull};
        ull a1[4] = {0ull, 0ull, 0ull, 0ull};
#pragma unroll 8
        for (int k2 = 0; k2 < 64; k2++) {
            ull w0 = sW1u[k2 * 64 + lane];
            ull w1 = sW1u[k2 * 64 + lane + 32];
#pragma unroll
            for (int m = 0; m < 4; m++) {
                ull b = mystgU[m * 64 + k2];
                FFMA2(a0[m], b, w0);
                FFMA2(a1[m], b, w1);
            }
        }
#pragma unroll
        for (int m = 0; m < 4; m++) {
            int n = g * 4 + m;
            const float* e = (n < N_ENT) ? (ent + (size_t)n * 64)
                                         : (usr + (size_t)(n - N_ENT) * 64);
            float q0 = (f2sum(a0[m]) + bb1a) - e[lane];
            float q1 = (f2sum(a1[m]) + bb1b) - e[lane + 32];
            lsum += q0 * q0 + q1 * q1;
        }
        __syncwarp();
    }
#pragma unroll
    for (int o = 16; o; o >>= 1) lsum += __shfl_xor_sync(0xffffffffu, lsum, o);
    if (lane == 0) atomicAdd(&g_loss, lsum);
}

// ---------------- per-node per-relation gate dots: gd/gs [N,16] ------------------
__global__ void __launch_bounds__(256) gate_kernel(int layer) {
    const float* x  = (layer == 1) ? g_encoded : g_x1;
    const float* ws = (layer == 1) ? g_wsum1 : g_wsum2;
    __shared__ float sWd[32 * 16];
    __shared__ float sWs[32 * 16];
    for (int i = threadIdx.x; i < NREL * 64; i += 256) {
        int r = i >> 6, k = i & 63;
        float v = ws[i];
        if (k < 32) sWd[k * 16 + r] = v;
        else        sWs[(k - 32) * 16 + r] = v;
    }
    __syncthreads();

    int wid = (blockIdx.x * 256 + threadIdx.x) >> 5;
    if (wid >= NND) return;
    int lane = threadIdx.x & 31;
    int r    = lane & 15;
    const float* base = (lane >= 16) ? sWs : sWd;
    float xv  = x[wid * 32 + lane];
    float acc = 0.f;
#pragma unroll
    for (int k = 0; k < 32; k++) {
        float b = __shfl_sync(0xffffffffu, xv, k);
        acc = fmaf(b, base[k * 16 + r], acc);
    }
    if (lane < 16) g_gd[wid * 16 + r] = acc;
    else           g_gs[wid * 16 + r] = acc;
}

// ---------------- gather: agg[d] = mean_e sigmoid(gate)*x[src]  (2 warps/node) ----
template <int LAYER>
__global__ void __launch_bounds__(256) gather_kernel() {
    const float* x = (LAYER == 1) ? g_encoded : g_x1;
    __shared__ float red[4][32];

    const int lane    = threadIdx.x & 31;
    const int half    = (threadIdx.x >> 5) & 1;
    const int pairloc = threadIdx.x >> 6;             // 0..3
    const int node    = blockIdx.x * 4 + pairloc;     // grid = NND/4 exactly

    int base = g_rowptr[node];
    int deg  = g_cnt[node];
    int d0   = (deg + 1) >> 1;
    int mybase = base + (half ? d0 : 0);
    int mycnt  = half ? (deg - d0) : d0;
    const float* gdn = g_gd + node * 16;

    float aggv = 0.f;
    int i = 0;
    for (; i + 8 <= mycnt; i += 8) {
        int p[8];
#pragma unroll
        for (int u = 0; u < 8; u++) p[u] = g_csr[mybase + i + u];
        float h[8], gl[8];
#pragma unroll
        for (int u = 0; u < 8; u++) {
            int s = p[u] & 0xFFFF, r = p[u] >> 16;
            h[u]  = x[(size_t)s * 32 + lane];
            gl[u] = gdn[r] + g_gs[s * 16 + r];
        }
#pragma unroll
        for (int u = 0; u < 8; u++) aggv = fmaf(h[u], sigmoidf_(gl[u]), aggv);
    }
    for (; i < mycnt; i++) {
        int p = g_csr[mybase + i];
        int s = p & 0xFFFF, r = p >> 16;
        aggv = fmaf(x[(size_t)s * 32 + lane], sigmoidf_(gdn[r] + g_gs[s * 16 + r]), aggv);
    }

    if (half) red[pairloc][lane] = aggv;
    __syncthreads();
    if (!half) {
        float inv = (deg > 0) ? (1.f / (float)deg) : 0.f;
        g_agg[(size_t)node * 32 + lane] = (aggv + red[pairloc][lane]) * inv;
    }
}

// ---------------- combine: leaky_relu(concat(x, agg) @ W + b) --------------------
template <int LAYER>
__global__ void __launch_bounds__(256) combine_kernel(const float* __restrict__ linW,
                                                      const float* __restrict__ linb) {
    constexpr int OUT = (LAYER == 1) ? 32 : 16;
    const float* x = (LAYER == 1) ? g_encoded : g_x1;
    float* xo      = (LAYER == 1) ? g_x1 : g_x2;
    __shared__ float sW[64 * OUT];
    for (int i = threadIdx.x; i < 64 * OUT; i += 256) sW[i] = linW[i];
    __syncthreads();

    int wid = (blockIdx.x * 256 + threadIdx.x) >> 5;
    if (wid >= NND) return;
    int lane = threadIdx.x & 31;
    int j    = lane & (OUT - 1);
    float xv = x[(size_t)wid * 32 + lane];
    float av = g_agg[(size_t)wid * 32 + lane];
    float acc = linb[j];
#pragma unroll
    for (int k = 0; k < 32; k++) {
        float b = __shfl_sync(0xffffffffu, xv, k);
        acc = fmaf(b, sW[k * OUT + j], acc);
    }
#pragma unroll
    for (int k = 0; k < 32; k++) {
        float b = __shfl_sync(0xffffffffu, av, k);
        acc = fmaf(b, sW[(32 + k) * OUT + j], acc);
    }
    acc = (acc > 0.f) ? acc : 0.01f * acc;
    if (lane < OUT) xo[(size_t)wid * OUT + lane] = acc;
}

// ---------------- scoring: dot(final[user_node], final[item]) --------------------
__global__ void __launch_bounds__(256) score_kernel(const int* __restrict__ users,
                                                    const int* __restrict__ items,
                                                    float* __restrict__ out) {
    int wid = (blockIdx.x * 256 + threadIdx.x) >> 5;
    if (wid >= BATCH) return;
    int lane = threadIdx.x & 31;
    int un = N_ENT + users[wid];
    int it = items[wid];
    float s = g_x1[(size_t)un * 32 + lane] * g_x1[(size_t)it * 32 + lane];
    if (lane < 16) s += g_x2[(size_t)un * 16 + lane] * g_x2[(size_t)it * 16 + lane];
#pragma unroll
    for (int o = 16; o; o >>= 1) s += __shfl_xor_sync(0xffffffffu, s, o);
    if (lane == 0) out[wid] = s;
}

// ---------------- finalize: write loss, then reset persistent accumulators -------
__global__ void __launch_bounds__(256) finalize_reset_kernel(float* out, int out_size) {
    int i = blockIdx.x * blockDim.x + threadIdx.x;
    if (i == 0) {
        if (out_size > BATCH) out[BATCH] = g_loss * (1.0f / (float)(NND * 64));
        g_loss = 0.f;
    }
    if (i < NND) g_cnt[i] = 0;   // restore invariant for next replay
}

// ---------------- host launcher --------------------------------------------------
extern "C" void kernel_launch(void* const* d_in, const int* in_sizes, int n_in,
                              void* d_out, int out_size) {
    int iu = 0, ii = 1, ies = 2, ied = 3, ier = 4, ient = 5, iusr = 6;
    int ie0 = 7, ib0 = 8, ie1 = 9, ib1 = 10, id0 = 11, idb0 = 12, id1 = 13, idb1 = 14;
    int iWr1 = 15, ilW1 = 16, ilb1 = 17, iWr2 = 18, ilW2 = 19, ilb2 = 20;
    bool dict_order = (n_in >= 21 && in_sizes[0] == BATCH && in_sizes[2] == NEDGE &&
                       in_sizes[5] == N_ENT * 64);
    if (!dict_order) {
        ient = 0; iusr = 1; ie0 = 2; ib0 = 3; ie1 = 4; ib1 = 5;
        id0 = 6; idb0 = 7; id1 = 8; idb1 = 9;
        iWr1 = 10; ilW1 = 11; ilb1 = 12; iWr2 = 13; ilW2 = 14; ilb2 = 15;
        iu = 16; ii = 17; ies = 18; ied = 19; ier = 20;
    }
    const int* users = (const int*)d_in[iu];
    const int* items = (const int*)d_in[ii];
    const int* esrc  = (const int*)d_in[ies];
    const int* edst  = (const int*)d_in[ied];
    const int* erel  = (const int*)d_in[ier];
    const float* ent = (const float*)d_in[ient];
    const float* usr = (const float*)d_in[iusr];
    float* out = (float*)d_out;

    static bool attr_done = false;
    if (!attr_done) {
        cudaFuncSetAttribute(encode_kernel, cudaFuncAttributeMaxDynamicSharedMemorySize, 65536);
        cudaFuncSetAttribute(decode_kernel, cudaFuncAttributeMaxDynamicSharedMemorySize, 65536);
        attr_done = true;
    }

    // CSR build (g_cnt arrives zeroed: static init on call 1, end-reset thereafter)
    count_kernel<<<(NEDGE + 255) / 256, 256>>>(edst);                 // launch 1
    scan_block_kernel<<<NBLK, 512>>>();                               // launch 2
    scan_add_kernel<<<NBLK, 512>>>();                                 // launch 3
    fill_kernel<<<(NEDGE + 255) / 256, 256>>>(esrc, edst, erel);      // launch 4 (profiled)

    wsum_kernel<<<8, 256>>>((const float*)d_in[iWr1], (const float*)d_in[iWr2]);
    encode_kernel<<<444, 256, 65536>>>(ent, usr,
                                (const float*)d_in[ie0], (const float*)d_in[ib0],
                                (const float*)d_in[ie1], (const float*)d_in[ib1]);
    // layer 1
    gate_kernel<<<(NND + 7) / 8, 256>>>(1);
    gather_kernel<1><<<NND / 4, 256>>>();
    combine_kernel<1><<<(NND + 7) / 8, 256>>>((const float*)d_in[ilW1],
                                              (const float*)d_in[ilb1]);
    // layer 2
    gate_kernel<<<(NND + 7) / 8, 256>>>(2);
    gather_kernel<2><<<NND / 4, 256>>>();
    combine_kernel<2><<<(NND + 7) / 8, 256>>>((const float*)d_in[ilW2],
                                              (const float*)d_in[ilb2]);
    // autoencoder loss (independent of conv path)
    decode_kernel<<<444, 256, 65536>>>(ent, usr,
                                (const float*)d_in[id0], (const float*)d_in[idb0],
                                (const float*)d_in[id1], (const float*)d_in[idb1]);
    // outputs + reset persistent state
    score_kernel<<<(BATCH * 32 + 255) / 256, 256>>>(users, items, out);
    finalize_reset_kernel<<<(NND + 255) / 256, 256>>>(out, out_size);
}

// round 5
// speedup vs baseline: 1.1098x; 1.1098x over previous
#include <cuda_runtime.h>
#include <cuda_bf16.h>
#include <cstdint>
#include <cstdio>

#define N_ENT 50000
#define N_USR 10000
#define NND   60000
#define NEDGE 1920000
#define NREL  16
#define BATCH 4096

typedef unsigned long long ull;

// packed f32x2 FMA: d.lo += a.lo*b.lo ; d.hi += a.hi*b.hi  (one issue slot, 2 FMAs)
#define FFMA2(d, a, b) asm("fma.rn.f32x2 %0, %1, %2, %0;" : "+l"(d) : "l"(a), "l"(b))

__device__ __forceinline__ float f2lo(ull v) { return __uint_as_float((unsigned)v); }
__device__ __forceinline__ float f2hi(ull v) { return __uint_as_float((unsigned)(v >> 32)); }
__device__ __forceinline__ float f2sum(ull v) { return f2lo(v) + f2hi(v); }
__device__ __forceinline__ float sigmoidf_(float g) { return 1.f / (1.f + __expf(-g)); }

// ---------------- scratch (device globals; zero-initialized; reset at END) -------
__device__ float g_encoded[NND * 32];
__device__ float g_x1[NND * 32];
__device__ float g_x2[NND * 16];
__device__ __align__(16) float g_agg1[NND * 32];   // layer-1 accumulator
__device__ __align__(16) float g_agg2[NND * 32];   // layer-2 accumulator
__device__ int   g_cnt[NND];                        // degree
__device__ float g_gd[NND * 16];
__device__ float g_gs[NND * 16];
__device__ float g_wsum1[NREL * 64];
__device__ float g_wsum2[NREL * 64];
__device__ float g_loss;

extern __shared__ unsigned char dynsmem[];

// ---------------- count (degree) + fused wsum (extra block) ----------------------
__global__ void __launch_bounds__(256) count_wsum_kernel(const int* __restrict__ edst,
                                                         const float* __restrict__ Wr1,
                                                         const float* __restrict__ Wr2) {
    if (blockIdx.x == gridDim.x - 1) {
        // w_sum = W_r.sum(-1) for both layers: 2048 outputs over 256 threads
        for (int i = threadIdx.x; i < 2 * NREL * 64; i += 256) {
            const float* W = (i < NREL * 64) ? Wr1 : Wr2;
            float* o       = (i < NREL * 64) ? g_wsum1 : g_wsum2;
            int j          = i & (NREL * 64 - 1);
            const float* p = W + j * 32;
            float s = 0.f;
#pragma unroll
            for (int t = 0; t < 32; t++) s += p[t];
            o[j] = s;
        }
        return;
    }
    int e = blockIdx.x * blockDim.x + threadIdx.x;
    if (e < NEDGE) atomicAdd(&g_cnt[edst[e]], 1);
}

// ---------------- autoencoder: encode ([64]->relu[128]->[32]) --------------------
__global__ void __launch_bounds__(256, 3) encode_kernel(
    const float* __restrict__ ent, const float* __restrict__ usr,
    const float* __restrict__ W0, const float* __restrict__ b0,
    const float* __restrict__ W1, const float* __restrict__ b1) {
    float2* sW0 = (float2*)dynsmem;               // 32 k-pairs x 128 cols  (32 KB)
    float2* sW1 = sW0 + 32 * 128;                 // 64 k-pairs x 32 cols   (16 KB)
    float*  stg = (float*)(sW1 + 64 * 32);        // 8 warps x 512 floats   (16 KB)

    for (int i = threadIdx.x; i < 32 * 128; i += 256) {
        int k2 = i >> 7, j = i & 127;
        sW0[i] = make_float2(W0[(2 * k2) * 128 + j], W0[(2 * k2 + 1) * 128 + j]);
    }
    for (int i = threadIdx.x; i < 64 * 32; i += 256) {
        int k2 = i >> 5, j = i & 31;
        sW1[i] = make_float2(W1[(2 * k2) * 32 + j], W1[(2 * k2 + 1) * 32 + j]);
    }
    __syncthreads();

    const ull* sW0u = (const ull*)sW0;
    const ull* sW1u = (const ull*)sW1;
    const int lane  = threadIdx.x & 31;
    float* mystg    = stg + (threadIdx.x >> 5) * 512;
    ull*   mystgU   = (ull*)mystg;

    const int wid   = (blockIdx.x * 256 + threadIdx.x) >> 5;
    const int nwarp = (gridDim.x * 256) >> 5;

    float bb0[4];
#pragma unroll
    for (int p = 0; p < 4; p++) bb0[p] = b0[lane + 32 * p];
    const float bb1 = b1[lane];

    for (int g = wid; g < NND / 4; g += nwarp) {
#pragma unroll
        for (int m = 0; m < 4; m++) {
            int n = g * 4 + m;
            const float* e = (n < N_ENT) ? (ent + (size_t)n * 64)
                                         : (usr + (size_t)(n - N_ENT) * 64);
            ((float2*)mystg)[m * 32 + lane] = ((const float2*)e)[lane];
        }
        __syncwarp();

        ull acc[4][4];
#pragma unroll
        for (int m = 0; m < 4; m++)
#pragma unroll
            for (int p = 0; p < 4; p++) acc[m][p] = 0ull;
#pragma unroll 8
        for (int k2 = 0; k2 < 32; k2++) {
            ull w0 = sW0u[k2 * 128 + lane];
            ull w1 = sW0u[k2 * 128 + lane + 32];
            ull w2 = sW0u[k2 * 128 + lane + 64];
            ull w3 = sW0u[k2 * 128 + lane + 96];
#pragma unroll
            for (int m = 0; m < 4; m++) {
                ull b = mystgU[m * 32 + k2];
                FFMA2(acc[m][0], b, w0);
                FFMA2(acc[m][1], b, w1);
                FFMA2(acc[m][2], b, w2);
                FFMA2(acc[m][3], b, w3);
            }
        }
        __syncwarp();

#pragma unroll
        for (int m = 0; m < 4; m++)
#pragma unroll
            for (int p = 0; p < 4; p++)
                mystg[m * 128 + lane + 32 * p] = fmaxf(f2sum(acc[m][p]) + bb0[p], 0.f);
        __syncwarp();

        ull a2[4] = {0ull, 0ull, 0ull, 0ull};
#pragma unroll 8
        for (int k2 = 0; k2 < 64; k2++) {
            ull w = sW1u[k2 * 32 + lane];
#pragma unroll
            for (int m = 0; m < 4; m++) {
                ull b = mystgU[m * 64 + k2];
                FFMA2(a2[m], b, w);
            }
        }
#pragma unroll
        for (int m = 0; m < 4; m++)
            g_encoded[(size_t)(g * 4 + m) * 32 + lane] = f2sum(a2[m]) + bb1;
        __syncwarp();
    }
}

// ---------------- autoencoder: decode ([32]->relu[128]->[64]) + sq-err loss ------
__global__ void __launch_bounds__(256, 3) decode_kernel(
    const float* __restrict__ ent, const float* __restrict__ usr,
    const float* __restrict__ W0, const float* __restrict__ b0,
    const float* __restrict__ W1, const float* __restrict__ b1) {
    float2* sW0 = (float2*)dynsmem;               // 16 k-pairs x 128 cols (16 KB)
    float2* sW1 = sW0 + 16 * 128;                 // 64 k-pairs x 64 cols  (32 KB)
    float*  stg = (float*)(sW1 + 64 * 64);        // 8 warps x 512 floats  (16 KB)

    for (int i = threadIdx.x; i < 16 * 128; i += 256) {
        int k2 = i >> 7, j = i & 127;
        sW0[i] = make_float2(W0[(2 * k2) * 128 + j], W0[(2 * k2 + 1) * 128 + j]);
    }
    for (int i = threadIdx.x; i < 64 * 64; i += 256) {
        int k2 = i >> 6, j = i & 63;
        sW1[i] = make_float2(W1[(2 * k2) * 64 + j], W1[(2 * k2 + 1) * 64 + j]);
    }
    __syncthreads();

    const ull* sW0u = (const ull*)sW0;
    const ull* sW1u = (const ull*)sW1;
    const int lane  = threadIdx.x & 31;
    float* mystg    = stg + (threadIdx.x >> 5) * 512;
    ull*   mystgU   = (ull*)mystg;

    const int wid   = (blockIdx.x * 256 + threadIdx.x) >> 5;
    const int nwarp = (gridDim.x * 256) >> 5;

    float bb0[4];
#pragma unroll
    for (int p = 0; p < 4; p++) bb0[p] = b0[lane + 32 * p];
    const float bb1a = b1[lane], bb1b = b1[lane + 32];

    float lsum = 0.f;
    for (int g = wid; g < NND / 4; g += nwarp) {
#pragma unroll
        for (int m = 0; m < 4; m++)
            mystg[m * 32 + lane] = g_encoded[(size_t)(g * 4 + m) * 32 + lane];
        __syncwarp();

        ull acc[4][4];
#pragma unroll
        for (int m = 0; m < 4; m++)
#pragma unroll
            for (int p = 0; p < 4; p++) acc[m][p] = 0ull;
#pragma unroll
        for (int k2 = 0; k2 < 16; k2++) {
            ull w0 = sW0u[k2 * 128 + lane];
            ull w1 = sW0u[k2 * 128 + lane + 32];
            ull w2 = sW0u[k2 * 128 + lane + 64];
            ull w3 = sW0u[k2 * 128 + lane + 96];
#pragma unroll
            for (int m = 0; m < 4; m++) {
                ull b = mystgU[m * 16 + k2];
                FFMA2(acc[m][0], b, w0);
                FFMA2(acc[m][1], b, w1);
                FFMA2(acc[m][2], b, w2);
                FFMA2(acc[m][3], b, w3);
            }
        }
        __syncwarp();
#pragma unroll
        for (int m = 0; m < 4; m++)
#pragma unroll
            for (int p = 0; p < 4; p++)
                mystg[m * 128 + lane + 32 * p] = fmaxf(f2sum(acc[m][p]) + bb0[p], 0.f);
        __syncwarp();

        ull a0[4] = {0ull, 0ull, 0ull, 0ull};
        ull a1[4] = {0ull, 0ull, 0ull, 0ull};
#pragma unroll 8
        for (int k2 = 0; k2 < 64; k2++) {
            ull w0 = sW1u[k2 * 64 + lane];
            ull w1 = sW1u[k2 * 64 + lane + 32];
#pragma unroll
            for (int m = 0; m < 4; m++) {
                ull b = mystgU[m * 64 + k2];
                FFMA2(a0[m], b, w0);
                FFMA2(a1[m], b, w1);
            }
        }
#pragma unroll
        for (int m = 0; m < 4; m++) {
            int n = g * 4 + m;
            const float* e = (n < N_ENT) ? (ent + (size_t)n * 64)
                                         : (usr + (size_t)(n - N_ENT) * 64);
            float q0 = (f2sum(a0[m]) + bb1a) - e[lane];
            float q1 = (f2sum(a1[m]) + bb1b) - e[lane + 32];
            lsum += q0 * q0 + q1 * q1;
        }
        __syncwarp();
    }
#pragma unroll
    for (int o = 16; o; o >>= 1) lsum += __shfl_xor_sync(0xffffffffu, lsum, o);
    if (lane == 0) atomicAdd(&g_loss, lsum);
}

// ---------------- per-node per-relation gate dots: gd/gs [N,16] ------------------
__global__ void __launch_bounds__(256) gate_kernel(int layer) {
    const float* x  = (layer == 1) ? g_encoded : g_x1;
    const float* ws = (layer == 1) ? g_wsum1 : g_wsum2;
    __shared__ float sWd[32 * 16];
    __shared__ float sWs[32 * 16];
    for (int i = threadIdx.x; i < NREL * 64; i += 256) {
        int r = i >> 6, k = i & 63;
        float v = ws[i];
        if (k < 32) sWd[k * 16 + r] = v;
        else        sWs[(k - 32) * 16 + r] = v;
    }
    __syncthreads();

    int wid = (blockIdx.x * 256 + threadIdx.x) >> 5;
    if (wid >= NND) return;
    int lane = threadIdx.x & 31;
    int r    = lane & 15;
    const float* base = (lane >= 16) ? sWs : sWd;
    float xv  = x[wid * 32 + lane];
    float acc = 0.f;
#pragma unroll
    for (int k = 0; k < 32; k++) {
        float b = __shfl_sync(0xffffffffu, xv, k);
        acc = fmaf(b, base[k * 16 + r], acc);
    }
    if (lane < 16) g_gd[wid * 16 + r] = acc;
    else           g_gs[wid * 16 + r] = acc;
}

// ---------------- edge scatter v2: warp = 4 edges; gate computed once/edge -------
// Lanes 0-3 compute gates + idx for the warp's 4 edges; shfl-broadcast to
// the 8-lane groups; each lane moves one float4 and issues one red.v4.
template <int LAYER>
__global__ void __launch_bounds__(256) edge_kernel(const int* __restrict__ esrc,
                                                   const int* __restrict__ edst,
                                                   const int* __restrict__ erel) {
    const float* x = (LAYER == 1) ? g_encoded : g_x1;
    float* agg     = (LAYER == 1) ? g_agg1 : g_agg2;

    const int lane = threadIdx.x & 31;
    const int g    = lane >> 3;           // which of the warp's 4 edges
    const int sub  = lane & 7;            // float4 slice within the 32-dim row
    const int e4   = ((blockIdx.x * 256 + threadIdx.x) >> 5) * 4;  // NEDGE % 32blk == 0

    float gate = 0.f; int s = 0, d = 0;
    if (lane < 4) {
        int e = e4 + lane;
        s = esrc[e]; d = edst[e];
        int r = erel[e];
        float gl = g_gd[d * 16 + r] + g_gs[s * 16 + r];
        gate = sigmoidf_(gl);
    }
    gate = __shfl_sync(0xffffffffu, gate, g);
    s    = __shfl_sync(0xffffffffu, s, g);
    d    = __shfl_sync(0xffffffffu, d, g);

    const float4 h = *reinterpret_cast<const float4*>(x + (size_t)s * 32 + sub * 4);
    float* a = agg + (size_t)d * 32 + sub * 4;
    asm volatile("red.global.add.v4.f32 [%0], {%1, %2, %3, %4};"
                 :: "l"(a), "f"(h.x * gate), "f"(h.y * gate),
                    "f"(h.z * gate), "f"(h.w * gate)
                 : "memory");
}

// ---------------- combine: leaky_relu(concat(x, mean-agg) @ W + b) ---------------
template <int LAYER>
__global__ void __launch_bounds__(256) combine_kernel(const float* __restrict__ linW,
                                                      const float* __restrict__ linb) {
    constexpr int OUT = (LAYER == 1) ? 32 : 16;
    const float* x   = (LAYER == 1) ? g_encoded : g_x1;
    const float* agg = (LAYER == 1) ? g_agg1 : g_agg2;
    float* xo        = (LAYER == 1) ? g_x1 : g_x2;
    __shared__ float sW[64 * OUT];
    for (int i = threadIdx.x; i < 64 * OUT; i += 256) sW[i] = linW[i];
    __syncthreads();

    int wid = (blockIdx.x * 256 + threadIdx.x) >> 5;
    if (wid >= NND) return;
    int lane = threadIdx.x & 31;
    int j    = lane & (OUT - 1);
    float xv = x[(size_t)wid * 32 + lane];
    int   c  = g_cnt[wid];
    float av = (c > 0) ? agg[(size_t)wid * 32 + lane] / (float)c : 0.f;
    float acc = linb[j];
#pragma unroll
    for (int k = 0; k < 32; k++) {
        float b = __shfl_sync(0xffffffffu, xv, k);
        acc = fmaf(b, sW[k * OUT + j], acc);
    }
#pragma unroll
    for (int k = 0; k < 32; k++) {
        float b = __shfl_sync(0xffffffffu, av, k);
        acc = fmaf(b, sW[(32 + k) * OUT + j], acc);
    }
    acc = (acc > 0.f) ? acc : 0.01f * acc;
    if (lane < OUT) xo[(size_t)wid * OUT + lane] = acc;
}

// ---------------- scoring: dot(final[user_node], final[item]) --------------------
__global__ void __launch_bounds__(256) score_kernel(const int* __restrict__ users,
                                                    const int* __restrict__ items,
                                                    float* __restrict__ out) {
    int wid = (blockIdx.x * 256 + threadIdx.x) >> 5;
    if (wid >= BATCH) return;
    int lane = threadIdx.x & 31;
    int un = N_ENT + users[wid];
    int it = items[wid];
    float s = g_x1[(size_t)un * 32 + lane] * g_x1[(size_t)it * 32 + lane];
    if (lane < 16) s += g_x2[(size_t)un * 16 + lane] * g_x2[(size_t)it * 16 + lane];
#pragma unroll
    for (int o = 16; o; o >>= 1) s += __shfl_xor_sync(0xffffffffu, s, o);
    if (lane == 0) out[wid] = s;
}

// ---------------- finalize: write loss; reset persistent accumulators ------------
__global__ void __launch_bounds__(256) finalize_reset_kernel(float* out, int out_size) {
    int i  = blockIdx.x * blockDim.x + threadIdx.x;
    int st = gridDim.x * blockDim.x;
    if (i == 0) {
        if (out_size > BATCH) out[BATCH] = g_loss * (1.0f / (float)(NND * 64));
        g_loss = 0.f;
    }
    for (int k = i; k < NND * 32; k += st) { g_agg1[k] = 0.f; g_agg2[k] = 0.f; }
    for (int k = i; k < NND; k += st) g_cnt[k] = 0;
}

// ---------------- host launcher --------------------------------------------------
extern "C" void kernel_launch(void* const* d_in, const int* in_sizes, int n_in,
                              void* d_out, int out_size) {
    int iu = 0, ii = 1, ies = 2, ied = 3, ier = 4, ient = 5, iusr = 6;
    int ie0 = 7, ib0 = 8, ie1 = 9, ib1 = 10, id0 = 11, idb0 = 12, id1 = 13, idb1 = 14;
    int iWr1 = 15, ilW1 = 16, ilb1 = 17, iWr2 = 18, ilW2 = 19, ilb2 = 20;
    bool dict_order = (n_in >= 21 && in_sizes[0] == BATCH && in_sizes[2] == NEDGE &&
                       in_sizes[5] == N_ENT * 64);
    if (!dict_order) {
        ient = 0; iusr = 1; ie0 = 2; ib0 = 3; ie1 = 4; ib1 = 5;
        id0 = 6; idb0 = 7; id1 = 8; idb1 = 9;
        iWr1 = 10; ilW1 = 11; ilb1 = 12; iWr2 = 13; ilW2 = 14; ilb2 = 15;
        iu = 16; ii = 17; ies = 18; ied = 19; ier = 20;
    }
    const int* users = (const int*)d_in[iu];
    const int* items = (const int*)d_in[ii];
    const int* esrc  = (const int*)d_in[ies];
    const int* edst  = (const int*)d_in[ied];
    const int* erel  = (const int*)d_in[ier];
    const float* ent = (const float*)d_in[ient];
    const float* usr = (const float*)d_in[iusr];
    float* out = (float*)d_out;

    static bool attr_done = false;
    if (!attr_done) {
        cudaFuncSetAttribute(encode_kernel, cudaFuncAttributeMaxDynamicSharedMemorySize, 65536);
        cudaFuncSetAttribute(decode_kernel, cudaFuncAttributeMaxDynamicSharedMemorySize, 65536);
        attr_done = true;
    }

    // (g_agg*, g_cnt, g_loss arrive zeroed: static init on call 1, end-reset after)
    count_wsum_kernel<<<(NEDGE + 255) / 256 + 1, 256>>>(edst,                 // launch 1
                                (const float*)d_in[iWr1], (const float*)d_in[iWr2]);
    encode_kernel<<<444, 256, 65536>>>(ent, usr,                              // launch 2
                                (const float*)d_in[ie0], (const float*)d_in[ib0],
                                (const float*)d_in[ie1], (const float*)d_in[ib1]);
    // layer 1
    gate_kernel<<<(NND + 7) / 8, 256>>>(1);                                   // launch 3
    edge_kernel<1><<<NEDGE / 32, 256>>>(esrc, edst, erel);                    // launch 4 (profiled)
    combine_kernel<1><<<(NND + 7) / 8, 256>>>((const float*)d_in[ilW1],
                                              (const float*)d_in[ilb1]);
    // layer 2
    gate_kernel<<<(NND + 7) / 8, 256>>>(2);
    edge_kernel<2><<<NEDGE / 32, 256>>>(esrc, edst, erel);
    combine_kernel<2><<<(NND + 7) / 8, 256>>>((const float*)d_in[ilW2],
                                              (const float*)d_in[ilb2]);
    // autoencoder loss (independent of conv path)
    decode_kernel<<<444, 256, 65536>>>(ent, usr,
                                (const float*)d_in[id0], (const float*)d_in[idb0],
                                (const float*)d_in[id1], (const float*)d_in[idb1]);
    // outputs + reset persistent state
    score_kernel<<<(BATCH * 32 + 255) / 256, 256>>>(users, items, out);
    finalize_reset_kernel<<<1920, 256>>>(out, out_size);
}

// round 6
// speedup vs baseline: 1.2671x; 1.1417x over previous
#include <cuda_runtime.h>
#include <cuda_bf16.h>
#include <cstdint>
#include <cstdio>

#define N_ENT 50000
#define N_USR 10000
#define NND   60000
#define NEDGE 1920000
#define NREL  16
#define BATCH 4096

typedef unsigned long long ull;

// packed f32x2 FMA: d.lo += a.lo*b.lo ; d.hi += a.hi*b.hi  (one issue slot, 2 FMAs)
#define FFMA2(d, a, b) asm("fma.rn.f32x2 %0, %1, %2, %0;" : "+l"(d) : "l"(a), "l"(b))

__device__ __forceinline__ float f2lo(ull v) { return __uint_as_float((unsigned)v); }
__device__ __forceinline__ float f2hi(ull v) { return __uint_as_float((unsigned)(v >> 32)); }
__device__ __forceinline__ float f2sum(ull v) { return f2lo(v) + f2hi(v); }
__device__ __forceinline__ float sigmoidf_(float g) { return 1.f / (1.f + __expf(-g)); }

// ---------------- scratch (device globals; zero-initialized; reset at END) -------
__device__ float g_encoded[NND * 32];
__device__ float g_x1[NND * 32];
__device__ float g_x2[NND * 16];
__device__ __align__(16) float g_agg1[NND * 32];
__device__ __align__(16) float g_agg2[NND * 32];
__device__ int   g_cnt[NND];
__device__ float g_gd[NND * 16];
__device__ float g_gs[NND * 16];
__device__ float g_wsum1[NREL * 64];
__device__ float g_wsum2[NREL * 64];
__device__ float g_loss;

extern __shared__ unsigned char dynsmem[];

// ---------------- w_sum = W_r.sum(-1) for both layers ----------------------------
__global__ void __launch_bounds__(256) wsum_kernel(const float* __restrict__ Wr1,
                                                   const float* __restrict__ Wr2) {
    int i = blockIdx.x * blockDim.x + threadIdx.x;
    if (i >= 2 * NREL * 64) return;
    const float* W = (i < NREL * 64) ? Wr1 : Wr2;
    float* o       = (i < NREL * 64) ? g_wsum1 : g_wsum2;
    int j          = i & (NREL * 64 - 1);
    const float* p = W + j * 32;
    float s = 0.f;
#pragma unroll
    for (int t = 0; t < 32; t++) s += p[t];
    o[j] = s;
}

// ---------------- degree count (side stream; overlapped with encode/edge1) -------
__global__ void __launch_bounds__(256) count_kernel(const int* __restrict__ edst) {
    int e = blockIdx.x * blockDim.x + threadIdx.x;
    if (e < NEDGE) atomicAdd(&g_cnt[edst[e]], 1);
}

// ---------------- encode ([64]->relu[128]->[32]) + fused gate-1 dots -------------
__global__ void __launch_bounds__(256, 3) encode_kernel(
    const float* __restrict__ ent, const float* __restrict__ usr,
    const float* __restrict__ W0, const float* __restrict__ b0,
    const float* __restrict__ W1, const float* __restrict__ b1) {
    float2* sW0 = (float2*)dynsmem;               // 32 k-pairs x 128 cols  (32 KB)
    float2* sW1 = sW0 + 32 * 128;                 // 64 k-pairs x 32 cols   (16 KB)
    float*  stg = (float*)(sW1 + 64 * 32);        // 8 warps x 512 floats   (16 KB)
    float*  sGd = stg + 8 * 512;                  // 32 x 16 (2 KB)
    float*  sGs = sGd + 32 * 16;                  // 32 x 16 (2 KB)  total 68 KB

    for (int i = threadIdx.x; i < 32 * 128; i += 256) {
        int k2 = i >> 7, j = i & 127;
        sW0[i] = make_float2(W0[(2 * k2) * 128 + j], W0[(2 * k2 + 1) * 128 + j]);
    }
    for (int i = threadIdx.x; i < 64 * 32; i += 256) {
        int k2 = i >> 5, j = i & 31;
        sW1[i] = make_float2(W1[(2 * k2) * 32 + j], W1[(2 * k2 + 1) * 32 + j]);
    }
    for (int i = threadIdx.x; i < NREL * 64; i += 256) {
        int r = i >> 6, k = i & 63;
        float v = g_wsum1[i];
        if (k < 32) sGd[k * 16 + r] = v;
        else        sGs[(k - 32) * 16 + r] = v;
    }
    __syncthreads();

    const ull* sW0u = (const ull*)sW0;
    const ull* sW1u = (const ull*)sW1;
    const int lane  = threadIdx.x & 31;
    float* mystg    = stg + (threadIdx.x >> 5) * 512;
    ull*   mystgU   = (ull*)mystg;

    const int wid   = (blockIdx.x * 256 + threadIdx.x) >> 5;
    const int nwarp = (gridDim.x * 256) >> 5;

    const int rr = lane & 15;
    const float* gb = (lane >= 16) ? sGs : sGd;

    float bb0[4];
#pragma unroll
    for (int p = 0; p < 4; p++) bb0[p] = b0[lane + 32 * p];
    const float bb1 = b1[lane];

    for (int g = wid; g < NND / 4; g += nwarp) {
#pragma unroll
        for (int m = 0; m < 4; m++) {
            int n = g * 4 + m;
            const float* e = (n < N_ENT) ? (ent + (size_t)n * 64)
                                         : (usr + (size_t)(n - N_ENT) * 64);
            ((float2*)mystg)[m * 32 + lane] = ((const float2*)e)[lane];
        }
        __syncwarp();

        ull acc[4][4];
#pragma unroll
        for (int m = 0; m < 4; m++)
#pragma unroll
            for (int p = 0; p < 4; p++) acc[m][p] = 0ull;
#pragma unroll 8
        for (int k2 = 0; k2 < 32; k2++) {
            ull w0 = sW0u[k2 * 128 + lane];
            ull w1 = sW0u[k2 * 128 + lane + 32];
            ull w2 = sW0u[k2 * 128 + lane + 64];
            ull w3 = sW0u[k2 * 128 + lane + 96];
#pragma unroll
            for (int m = 0; m < 4; m++) {
                ull b = mystgU[m * 32 + k2];
                FFMA2(acc[m][0], b, w0);
                FFMA2(acc[m][1], b, w1);
                FFMA2(acc[m][2], b, w2);
                FFMA2(acc[m][3], b, w3);
            }
        }
        __syncwarp();

#pragma unroll
        for (int m = 0; m < 4; m++)
#pragma unroll
            for (int p = 0; p < 4; p++)
                mystg[m * 128 + lane + 32 * p] = fmaxf(f2sum(acc[m][p]) + bb0[p], 0.f);
        __syncwarp();

        ull a2[4] = {0ull, 0ull, 0ull, 0ull};
#pragma unroll 8
        for (int k2 = 0; k2 < 64; k2++) {
            ull w = sW1u[k2 * 32 + lane];
#pragma unroll
            for (int m = 0; m < 4; m++) {
                ull b = mystgU[m * 64 + k2];
                FFMA2(a2[m], b, w);
            }
        }
#pragma unroll
        for (int m = 0; m < 4; m++) {
            int node = g * 4 + m;
            float v = f2sum(a2[m]) + bb1;
            g_encoded[(size_t)node * 32 + lane] = v;
            // fused gate-1 dots: gd[node,r] / gs[node,r]
            float ga = 0.f;
#pragma unroll
            for (int k = 0; k < 32; k++) {
                float b = __shfl_sync(0xffffffffu, v, k);
                ga = fmaf(b, gb[k * 16 + rr], ga);
            }
            if (lane < 16) g_gd[node * 16 + rr] = ga;
            else           g_gs[node * 16 + rr] = ga;
        }
        __syncwarp();
    }
}

// ---------------- decode ([32]->relu[128]->[64]) + sq-err loss (side stream) -----
__global__ void __launch_bounds__(256, 3) decode_kernel(
    const float* __restrict__ ent, const float* __restrict__ usr,
    const float* __restrict__ W0, const float* __restrict__ b0,
    const float* __restrict__ W1, const float* __restrict__ b1) {
    float2* sW0 = (float2*)dynsmem;               // 16 k-pairs x 128 cols (16 KB)
    float2* sW1 = sW0 + 16 * 128;                 // 64 k-pairs x 64 cols  (32 KB)
    float*  stg = (float*)(sW1 + 64 * 64);        // 8 warps x 512 floats  (16 KB)

    for (int i = threadIdx.x; i < 16 * 128; i += 256) {
        int k2 = i >> 7, j = i & 127;
        sW0[i] = make_float2(W0[(2 * k2) * 128 + j], W0[(2 * k2 + 1) * 128 + j]);
    }
    for (int i = threadIdx.x; i < 64 * 64; i += 256) {
        int k2 = i >> 6, j = i & 63;
        sW1[i] = make_float2(W1[(2 * k2) * 64 + j], W1[(2 * k2 + 1) * 64 + j]);
    }
    __syncthreads();

    const ull* sW0u = (const ull*)sW0;
    const ull* sW1u = (const ull*)sW1;
    const int lane  = threadIdx.x & 31;
    float* mystg    = stg + (threadIdx.x >> 5) * 512;
    ull*   mystgU   = (ull*)mystg;

    const int wid   = (blockIdx.x * 256 + threadIdx.x) >> 5;
    const int nwarp = (gridDim.x * 256) >> 5;

    float bb0[4];
#pragma unroll
    for (int p = 0; p < 4; p++) bb0[p] = b0[lane + 32 * p];
    const float bb1a = b1[lane], bb1b = b1[lane + 32];

    float lsum = 0.f;
    for (int g = wid; g < NND / 4; g += nwarp) {
#pragma unroll
        for (int m = 0; m < 4; m++)
            mystg[m * 32 + lane] = g_encoded[(size_t)(g * 4 + m) * 32 + lane];
        __syncwarp();

        ull acc[4][4];
#pragma unroll
        for (int m = 0; m < 4; m++)
#pragma unroll
            for (int p = 0; p < 4; p++) acc[m][p] = 0ull;
#pragma unroll
        for (int k2 = 0; k2 < 16; k2++) {
            ull w0 = sW0u[k2 * 128 + lane];
            ull w1 = sW0u[k2 * 128 + lane + 32];
            ull w2 = sW0u[k2 * 128 + lane + 64];
            ull w3 = sW0u[k2 * 128 + lane + 96];
#pragma unroll
            for (int m = 0; m < 4; m++) {
                ull b = mystgU[m * 16 + k2];
                FFMA2(acc[m][0], b, w0);
                FFMA2(acc[m][1], b, w1);
                FFMA2(acc[m][2], b, w2);
                FFMA2(acc[m][3], b, w3);
            }
        }
        __syncwarp();
#pragma unroll
        for (int m = 0; m < 4; m++)
#pragma unroll
            for (int p = 0; p < 4; p++)
                mystg[m * 128 + lane + 32 * p] = fmaxf(f2sum(acc[m][p]) + bb0[p], 0.f);
        __syncwarp();

        ull a0[4] = {0ull, 0ull, 0ull, 0ull};
        ull a1[4] = {0ull, 0ull, 0ull, 0ull};
#pragma unroll 8
        for (int k2 = 0; k2 < 64; k2++) {
            ull w0 = sW1u[k2 * 64 + lane];
            ull w1 = sW1u[k2 * 64 + lane + 32];
#pragma unroll
            for (int m = 0; m < 4; m++) {
                ull b = mystgU[m * 64 + k2];
                FFMA2(a0[m], b, w0);
                FFMA2(a1[m], b, w1);
            }
        }
#pragma unroll
        for (int m = 0; m < 4; m++) {
            int n = g * 4 + m;
            const float* e = (n < N_ENT) ? (ent + (size_t)n * 64)
                                         : (usr + (size_t)(n - N_ENT) * 64);
            float q0 = (f2sum(a0[m]) + bb1a) - e[lane];
            float q1 = (f2sum(a1[m]) + bb1b) - e[lane + 32];
            lsum += q0 * q0 + q1 * q1;
        }
        __syncwarp();
    }
#pragma unroll
    for (int o = 16; o; o >>= 1) lsum += __shfl_xor_sync(0xffffffffu, lsum, o);
    if (lane == 0) atomicAdd(&g_loss, lsum);
}

// ---------------- edge scatter v2: warp = 4 edges; gate computed once/edge -------
template <int LAYER>
__global__ void __launch_bounds__(256) edge_kernel(const int* __restrict__ esrc,
                                                   const int* __restrict__ edst,
                                                   const int* __restrict__ erel) {
    const float* x = (LAYER == 1) ? g_encoded : g_x1;
    float* agg     = (LAYER == 1) ? g_agg1 : g_agg2;

    const int lane = threadIdx.x & 31;
    const int g    = lane >> 3;
    const int sub  = lane & 7;
    const int e4   = ((blockIdx.x * 256 + threadIdx.x) >> 5) * 4;

    float gate = 0.f; int s = 0, d = 0;
    if (lane < 4) {
        int e = e4 + lane;
        s = esrc[e]; d = edst[e];
        int r = erel[e];
        float gl = g_gd[d * 16 + r] + g_gs[s * 16 + r];
        gate = sigmoidf_(gl);
    }
    gate = __shfl_sync(0xffffffffu, gate, g);
    s    = __shfl_sync(0xffffffffu, s, g);
    d    = __shfl_sync(0xffffffffu, d, g);

    const float4 h = *reinterpret_cast<const float4*>(x + (size_t)s * 32 + sub * 4);
    float* a = agg + (size_t)d * 32 + sub * 4;
    asm volatile("red.global.add.v4.f32 [%0], {%1, %2, %3, %4};"
                 :: "l"(a), "f"(h.x * gate), "f"(h.y * gate),
                    "f"(h.z * gate), "f"(h.w * gate)
                 : "memory");
}

// ---------------- combine (+ fused gate-2 dots for layer 1) ----------------------
template <int LAYER>
__global__ void __launch_bounds__(256) combine_kernel(const float* __restrict__ linW,
                                                      const float* __restrict__ linb) {
    constexpr int OUT = (LAYER == 1) ? 32 : 16;
    const float* x   = (LAYER == 1) ? g_encoded : g_x1;
    const float* agg = (LAYER == 1) ? g_agg1 : g_agg2;
    float* xo        = (LAYER == 1) ? g_x1 : g_x2;
    __shared__ float sW[64 * OUT];
    __shared__ float sGd[32 * 16];
    __shared__ float sGs[32 * 16];
    for (int i = threadIdx.x; i < 64 * OUT; i += 256) sW[i] = linW[i];
    if (LAYER == 1) {
        for (int i = threadIdx.x; i < NREL * 64; i += 256) {
            int r = i >> 6, k = i & 63;
            float v = g_wsum2[i];
            if (k < 32) sGd[k * 16 + r] = v;
            else        sGs[(k - 32) * 16 + r] = v;
        }
    }
    __syncthreads();

    int wid = (blockIdx.x * 256 + threadIdx.x) >> 5;
    if (wid >= NND) return;
    int lane = threadIdx.x & 31;
    int j    = lane & (OUT - 1);
    float xv = x[(size_t)wid * 32 + lane];
    int   c  = g_cnt[wid];
    float av = (c > 0) ? agg[(size_t)wid * 32 + lane] / (float)c : 0.f;
    float acc = linb[j];
#pragma unroll
    for (int k = 0; k < 32; k++) {
        float b = __shfl_sync(0xffffffffu, xv, k);
        acc = fmaf(b, sW[k * OUT + j], acc);
    }
#pragma unroll
    for (int k = 0; k < 32; k++) {
        float b = __shfl_sync(0xffffffffu, av, k);
        acc = fmaf(b, sW[(32 + k) * OUT + j], acc);
    }
    acc = (acc > 0.f) ? acc : 0.01f * acc;
    if (lane < OUT) xo[(size_t)wid * OUT + lane] = acc;

    if (LAYER == 1) {
        // fused gate-2 dots from x1 (= acc, valid on all 32 lanes since OUT=32)
        int rr = lane & 15;
        const float* gb = (lane >= 16) ? sGs : sGd;
        float ga = 0.f;
#pragma unroll
        for (int k = 0; k < 32; k++) {
            float b = __shfl_sync(0xffffffffu, acc, k);
            ga = fmaf(b, gb[k * 16 + rr], ga);
        }
        if (lane < 16) g_gd[wid * 16 + rr] = ga;
        else           g_gs[wid * 16 + rr] = ga;
    }
}

// ---------------- scoring: dot(final[user_node], final[item]) --------------------
__global__ void __launch_bounds__(256) score_kernel(const int* __restrict__ users,
                                                    const int* __restrict__ items,
                                                    float* __restrict__ out) {
    int wid = (blockIdx.x * 256 + threadIdx.x) >> 5;
    if (wid >= BATCH) return;
    int lane = threadIdx.x & 31;
    int un = N_ENT + users[wid];
    int it = items[wid];
    float s = g_x1[(size_t)un * 32 + lane] * g_x1[(size_t)it * 32 + lane];
    if (lane < 16) s += g_x2[(size_t)un * 16 + lane] * g_x2[(size_t)it * 16 + lane];
#pragma unroll
    for (int o = 16; o; o >>= 1) s += __shfl_xor_sync(0xffffffffu, s, o);
    if (lane == 0) out[wid] = s;
}

// ---------------- finalize: write loss; reset persistent accumulators ------------
__global__ void __launch_bounds__(256) finalize_reset_kernel(float* out, int out_size) {
    int i  = blockIdx.x * blockDim.x + threadIdx.x;
    int st = gridDim.x * blockDim.x;
    if (i == 0) {
        if (out_size > BATCH) out[BATCH] = g_loss * (1.0f / (float)(NND * 64));
        g_loss = 0.f;
    }
    for (int k = i; k < NND * 32; k += st) { g_agg1[k] = 0.f; g_agg2[k] = 0.f; }
    for (int k = i; k < NND; k += st) g_cnt[k] = 0;
}

// ---------------- host launcher (multi-stream fork/join; capture-legal) ----------
extern "C" void kernel_launch(void* const* d_in, const int* in_sizes, int n_in,
                              void* d_out, int out_size) {
    int iu = 0, ii = 1, ies = 2, ied = 3, ier = 4, ient = 5, iusr = 6;
    int ie0 = 7, ib0 = 8, ie1 = 9, ib1 = 10, id0 = 11, idb0 = 12, id1 = 13, idb1 = 14;
    int iWr1 = 15, ilW1 = 16, ilb1 = 17, iWr2 = 18, ilW2 = 19, ilb2 = 20;
    bool dict_order = (n_in >= 21 && in_sizes[0] == BATCH && in_sizes[2] == NEDGE &&
                       in_sizes[5] == N_ENT * 64);
    if (!dict_order) {
        ient = 0; iusr = 1; ie0 = 2; ib0 = 3; ie1 = 4; ib1 = 5;
        id0 = 6; idb0 = 7; id1 = 8; idb1 = 9;
        iWr1 = 10; ilW1 = 11; ilb1 = 12; iWr2 = 13; ilW2 = 14; ilb2 = 15;
        iu = 16; ii = 17; ies = 18; ied = 19; ier = 20;
    }
    const int* users = (const int*)d_in[iu];
    const int* items = (const int*)d_in[ii];
    const int* esrc  = (const int*)d_in[ies];
    const int* edst  = (const int*)d_in[ied];
    const int* erel  = (const int*)d_in[ier];
    const float* ent = (const float*)d_in[ient];
    const float* usr = (const float*)d_in[iusr];
    float* out = (float*)d_out;

    static cudaStream_t sCnt = nullptr, sDec = nullptr;
    static cudaEvent_t  eRoot = nullptr, eCnt = nullptr, eEnc = nullptr, eDec = nullptr;
    if (!sCnt) {
        cudaStreamCreateWithFlags(&sCnt, cudaStreamNonBlocking);
        cudaStreamCreateWithFlags(&sDec, cudaStreamNonBlocking);
        cudaEventCreateWithFlags(&eRoot, cudaEventDisableTiming);
        cudaEventCreateWithFlags(&eCnt,  cudaEventDisableTiming);
        cudaEventCreateWithFlags(&eEnc,  cudaEventDisableTiming);
        cudaEventCreateWithFlags(&eDec,  cudaEventDisableTiming);
        cudaFuncSetAttribute(encode_kernel, cudaFuncAttributeMaxDynamicSharedMemorySize, 69632);
        cudaFuncSetAttribute(decode_kernel, cudaFuncAttributeMaxDynamicSharedMemorySize, 65536);
    }

    // (g_agg*, g_cnt, g_loss arrive zeroed: static init on call 1, end-reset after)
    wsum_kernel<<<8, 256>>>((const float*)d_in[iWr1], (const float*)d_in[iWr2]);
    cudaEventRecord(eRoot, 0);

    // side stream 1: degree count (needed only by combine1/combine2)
    cudaStreamWaitEvent(sCnt, eRoot, 0);
    count_kernel<<<(NEDGE + 255) / 256, 256, 0, sCnt>>>(edst);
    cudaEventRecord(eCnt, sCnt);

    // main: encode (+ fused gate-1)
    encode_kernel<<<444, 256, 69632>>>(ent, usr,
                                (const float*)d_in[ie0], (const float*)d_in[ib0],
                                (const float*)d_in[ie1], (const float*)d_in[ib1]);
    cudaEventRecord(eEnc, 0);

    // side stream 2: decode/loss, overlapped with edge1
    cudaStreamWaitEvent(sDec, eEnc, 0);
    decode_kernel<<<444, 256, 65536, sDec>>>(ent, usr,
                                (const float*)d_in[id0], (const float*)d_in[idb0],
                                (const float*)d_in[id1], (const float*)d_in[idb1]);
    cudaEventRecord(eDec, sDec);

    // layer 1
    edge_kernel<1><<<NEDGE / 32, 256>>>(esrc, edst, erel);
    cudaStreamWaitEvent(0, eCnt, 0);
    combine_kernel<1><<<(NND + 7) / 8, 256>>>((const float*)d_in[ilW1],
                                              (const float*)d_in[ilb1]);
    // layer 2
    edge_kernel<2><<<NEDGE / 32, 256>>>(esrc, edst, erel);
    combine_kernel<2><<<(NND + 7) / 8, 256>>>((const float*)d_in[ilW2],
                                              (const float*)d_in[ilb2]);
    // outputs; join decode before reading g_loss
    score_kernel<<<(BATCH * 32 + 255) / 256, 256>>>(users, items, out);
    cudaStreamWaitEvent(0, eDec, 0);
    finalize_reset_kernel<<<1920, 256>>>(out, out_size);
}